// round 5
// baseline (speedup 1.0000x reference)
#include <cuda_runtime.h>
#include <cuda_bf16.h>

#define N_DIM 8
#define O_DIM 20
#define P_DIM 20
#define NTOT 32768
#define THREADS 128   // 4 samples/thread (2 packed f32x2 pairs) -> 512 samples/CTA

typedef unsigned long long ull;
#define ONE2 0x3F8000003F800000ULL

// Per-(perm,chain) partial sums: [P*7][N]
__device__ float g_scratch[P_DIM * 7 * NTOT];
// Per-perm partial sums: [P][N][2]
__device__ float g_pred[P_DIM * NTOT * 2];

__constant__ float c_binom[O_DIM] = {
    1.f, 19.f, 171.f, 969.f, 3876.f, 11628.f, 27132.f, 50388.f, 75582.f, 92378.f,
    92378.f, 75582.f, 50388.f, 27132.f, 11628.f, 3876.f, 969.f, 171.f, 19.f, 1.f};
__constant__ float c_cinv[6] = {1.0f, 1.f / 2, 1.f / 6, 1.f / 24, 1.f / 120, 1.f / 720};

// ---------------- packed f32x2 helpers ----------------
__device__ __forceinline__ ull fma2(ull a, ull b, ull c) {
    ull d; asm("fma.rn.f32x2 %0, %1, %2, %3;" : "=l"(d) : "l"(a), "l"(b), "l"(c)); return d;
}
__device__ __forceinline__ ull mul2(ull a, ull b) {
    ull d; asm("mul.rn.f32x2 %0, %1, %2;" : "=l"(d) : "l"(a), "l"(b)); return d;
}
__device__ __forceinline__ ull add2(ull a, ull b) {
    ull d; asm("add.rn.f32x2 %0, %1, %2;" : "=l"(d) : "l"(a), "l"(b)); return d;
}
__device__ __forceinline__ ull pack2(float lo, float hi) {
    ull d; asm("mov.b64 %0, {%1, %2};" : "=l"(d) : "f"(lo), "f"(hi)); return d;
}
__device__ __forceinline__ void unpack2(ull v, float& lo, float& hi) {
    asm("mov.b64 {%0, %1}, %2;" : "=f"(lo), "=f"(hi) : "l"(v));
}

// Dynamic smem (bytes):
//   sW2   : 7*200 ulonglong2 (duplicated pairs)  = 22400
//   sXx / sXomx : [8][2][128] ull each           = 16384 * 2
//   sW02  : 20 ull                               = 160
//   sPerm : 8 int                                = 32
#define SMEM_BYTES (22400 + 32768 + 160 + 32)

// One CTA = one (perm p, chain c) over a 512-sample tile. W exp'd inline.
__global__ __launch_bounds__(THREADS, 2) void main_kernel(
    const float* __restrict__ X, const int* __restrict__ perm,
    const float* __restrict__ meanw0, const float* __restrict__ meanw,
    const float* __restrict__ varw0, const float* __restrict__ varw, int ntiles) {
    extern __shared__ char smem[];
    ulonglong2* sW2 = (ulonglong2*)smem;                   // 22400 B
    ull* sXx = (ull*)(smem + 22400);                       // [8][2][128]
    ull* sXomx = sXx + 8 * 2 * THREADS;
    ull* sW02 = sXomx + 8 * 2 * THREADS;                   // 20 ull
    int* sPerm = (int*)(sW02 + O_DIM);

    const int t = threadIdx.x;
    const int tile = blockIdx.x % ntiles;
    const int pc = blockIdx.x / ntiles;                    // p*7 + c
    const int p = pc / 7;
    const int c = pc % 7;
    const int nA = (tile * THREADS + t) * 4;               // 4 consecutive samples

    if (t < N_DIM) sPerm[t] = perm[p * N_DIM + t];

    // ---- inline W prep: exp + binom column scale, duplicated (w,w) pairs ----
    ull* sW = (ull*)sW2;
    if (c == 0) {
#pragma unroll 1
        for (int j = t; j < 2800; j += THREADS) {
            int i = j / 400, oq = j % 400, q = j % 20;
            float w = __expf(meanw[(i * 20 + p) * 400 + oq]) * c_binom[q];
            sW[j] = pack2(w, w);
        }
        if (t < O_DIM) {
            float w = __expf(meanw0[p * 20 + t]) * c_binom[t];
            sW02[t] = pack2(w, w);
        }
    } else {
        const float kf = (float)c;
#pragma unroll 1
        for (int j = t; j < 2800; j += THREADS) {
            int i = j / 400, oq = j % 400, q = j % 20;
            int base = (i * 20 + p) * 400 + oq;
            float w = __expf(2.0f * meanw[base] + kf * varw[base]) *
                      (c_binom[q] * c_binom[q]);
            sW[j] = pack2(w, w);
        }
        if (t < O_DIM) {
            float w = __expf(2.0f * meanw0[p * 20 + t] + kf * varw0[p * 20 + t]) *
                      (c_binom[t] * c_binom[t]) * c_cinv[c - 1];
            sW02[t] = pack2(w, w);
        }
    }

    // ---- stage gates: (x, 1-x), squared for variance chains (c > 0) ----
    {
        const float4* XA = (const float4*)(X + (size_t)nA * N_DIM);
        float xs[4][8];
#pragma unroll
        for (int s = 0; s < 4; ++s) {
            float4 a = XA[2 * s], b = XA[2 * s + 1];
            xs[s][0] = a.x; xs[s][1] = a.y; xs[s][2] = a.z; xs[s][3] = a.w;
            xs[s][4] = b.x; xs[s][5] = b.y; xs[s][6] = b.z; xs[s][7] = b.w;
        }
        const bool sq = (c != 0);
#pragma unroll
        for (int d = 0; d < N_DIM; ++d) {
#pragma unroll
            for (int pr = 0; pr < 2; ++pr) {
                float xa = xs[2 * pr][d], xb = xs[2 * pr + 1][d];
                float oa = 1.0f - xa, ob = 1.0f - xb;
                if (sq) { xa *= xa; xb *= xb; oa *= oa; ob *= ob; }
                int idx = (d * 2 + pr) * THREADS + t;
                sXx[idx] = pack2(xa, xb);
                sXomx[idx] = pack2(oa, ob);
            }
        }
    }
    __syncthreads();

    // ---- chain: initial gate step ----
    ull f1[O_DIM], f2[O_DIM];
    {
        const int d0 = sPerm[0];
        const ull x1 = sXx[(d0 * 2 + 0) * THREADS + t];
        const ull x2 = sXx[(d0 * 2 + 1) * THREADS + t];
        const ull o1 = sXomx[(d0 * 2 + 0) * THREADS + t];
        const ull o2 = sXomx[(d0 * 2 + 1) * THREADS + t];
        ull px1 = ONE2, px2 = ONE2;
        f1[0] = sW02[0]; f2[0] = sW02[0];
#pragma unroll
        for (int q = 1; q < O_DIM; ++q) {
            px1 = mul2(px1, x1); px2 = mul2(px2, x2);
            f1[q] = mul2(sW02[q], px1);
            f2[q] = mul2(sW02[q], px2);
        }
        ull qk1 = ONE2, qk2 = ONE2;
#pragma unroll
        for (int q = O_DIM - 2; q >= 0; --q) {
            qk1 = mul2(qk1, o1); qk2 = mul2(qk2, o2);
            f1[q] = mul2(f1[q], qk1);
            f2[q] = mul2(f2[q], qk2);
        }
    }
    // ---- mid steps i = 1..6 ----
#pragma unroll 1
    for (int i = 1; i < N_DIM - 1; ++i) {
        const int di = sPerm[i];
        const ull x1 = sXx[(di * 2 + 0) * THREADS + t];
        const ull x2 = sXx[(di * 2 + 1) * THREADS + t];
        const ull o1 = sXomx[(di * 2 + 0) * THREADS + t];
        const ull o2 = sXomx[(di * 2 + 1) * THREADS + t];
        ull g1[O_DIM], g2[O_DIM];
#pragma unroll
        for (int q = 0; q < O_DIM; ++q) { g1[q] = 0ULL; g2[q] = 0ULL; }
        const ulonglong2* wbase = sW2 + (i - 1) * 200;
#pragma unroll
        for (int o = 0; o < O_DIM; ++o) {
            const ull a1 = f1[o];
            const ull a2 = f2[o];
            const ulonglong2* wr = wbase + o * 10;
#pragma unroll
            for (int j = 0; j < 10; ++j) {
                ulonglong2 w = wr[j];   // (w2q,w2q | w2q+1,w2q+1)
                g1[2 * j]     = fma2(a1, w.x, g1[2 * j]);
                g2[2 * j]     = fma2(a2, w.x, g2[2 * j]);
                g1[2 * j + 1] = fma2(a1, w.y, g1[2 * j + 1]);
                g2[2 * j + 1] = fma2(a2, w.y, g2[2 * j + 1]);
            }
        }
        ull px1 = ONE2, px2 = ONE2;
        f1[0] = g1[0]; f2[0] = g2[0];
#pragma unroll
        for (int q = 1; q < O_DIM; ++q) {
            px1 = mul2(px1, x1); px2 = mul2(px2, x2);
            f1[q] = mul2(g1[q], px1);
            f2[q] = mul2(g2[q], px2);
        }
        ull qk1 = ONE2, qk2 = ONE2;
#pragma unroll
        for (int q = O_DIM - 2; q >= 0; --q) {
            qk1 = mul2(qk1, o1); qk2 = mul2(qk2, o2);
            f1[q] = mul2(f1[q], qk1);
            f2[q] = mul2(f2[q], qk2);
        }
    }
    // ---- last step (i = 7): matmul + gate-pass-1 + fma-dot with qk ----
    float s0, s1, s2, s3;
    {
        const int di = sPerm[7];
        const ull x1 = sXx[(di * 2 + 0) * THREADS + t];
        const ull x2 = sXx[(di * 2 + 1) * THREADS + t];
        const ull o1 = sXomx[(di * 2 + 0) * THREADS + t];
        const ull o2 = sXomx[(di * 2 + 1) * THREADS + t];
        ull g1[O_DIM], g2[O_DIM];
#pragma unroll
        for (int q = 0; q < O_DIM; ++q) { g1[q] = 0ULL; g2[q] = 0ULL; }
        const ulonglong2* wbase = sW2 + 6 * 200;
#pragma unroll
        for (int o = 0; o < O_DIM; ++o) {
            const ull a1 = f1[o];
            const ull a2 = f2[o];
            const ulonglong2* wr = wbase + o * 10;
#pragma unroll
            for (int j = 0; j < 10; ++j) {
                ulonglong2 w = wr[j];
                g1[2 * j]     = fma2(a1, w.x, g1[2 * j]);
                g2[2 * j]     = fma2(a2, w.x, g2[2 * j]);
                g1[2 * j + 1] = fma2(a1, w.y, g1[2 * j + 1]);
                g2[2 * j + 1] = fma2(a2, w.y, g2[2 * j + 1]);
            }
        }
        // pass 1: scale by x^q (ascending running product)
        ull px1 = ONE2, px2 = ONE2;
#pragma unroll
        for (int q = 1; q < O_DIM; ++q) {
            px1 = mul2(px1, x1); px2 = mul2(px2, x2);
            g1[q] = mul2(g1[q], px1);
            g2[q] = mul2(g2[q], px2);
        }
        // pass 2: fma-dot with (1-x)^(19-q), two alternating accumulators
        ull se1 = g1[19], so1 = 0ULL, se2 = g2[19], so2 = 0ULL;
        ull qk1 = ONE2, qk2 = ONE2;
#pragma unroll
        for (int q = O_DIM - 2; q >= 0; --q) {
            qk1 = mul2(qk1, o1); qk2 = mul2(qk2, o2);
            if (q & 1) {
                so1 = fma2(g1[q], qk1, so1);
                so2 = fma2(g2[q], qk2, so2);
            } else {
                se1 = fma2(g1[q], qk1, se1);
                se2 = fma2(g2[q], qk2, se2);
            }
        }
        unpack2(add2(se1, so1), s0, s1);
        unpack2(add2(se2, so2), s2, s3);
    }
    *(float4*)(g_scratch + (size_t)pc * NTOT + nA) = make_float4(s0, s1, s2, s3);
}

// Stage 1: fold the 7 chains of each perm -> (mean, var) per (p, n).
__global__ void reduce1_kernel(int n) {
    int i = blockIdx.x * blockDim.x + threadIdx.x;   // i = p*n + nn
    if (i >= P_DIM * n) return;
    int p = i / n;
    int nn = i - p * n;
    float m = g_scratch[(size_t)(p * 7) * NTOT + nn];
    float v = 0.0f;
#pragma unroll
    for (int c = 1; c < 7; ++c)
        v += g_scratch[(size_t)(p * 7 + c) * NTOT + nn];
    *(float2*)(g_pred + (size_t)i * 2) = make_float2(m, v);
}

// Stage 2: sum over perms -> out[n][2].
__global__ void reduce2_kernel(float* __restrict__ out, int n) {
    int i = blockIdx.x * blockDim.x + threadIdx.x;
    if (i >= n) return;
    float m = 0.0f, v = 0.0f;
#pragma unroll
    for (int p = 0; p < P_DIM; ++p) {
        const float2 s = *(const float2*)(g_pred + ((size_t)p * n + i) * 2);
        m += s.x;
        v += s.y;
    }
    ((float2*)out)[i] = make_float2(m, v);
}

extern "C" void kernel_launch(void* const* d_in, const int* in_sizes, int n_in,
                              void* d_out, int out_size) {
    const float* X = (const float*)d_in[0];       // [N, 8]
    const int* perm = (const int*)d_in[1];        // [20, 8]
    const float* meanw0 = (const float*)d_in[2];  // [20, 1, 20]
    const float* meanw = (const float*)d_in[3];   // [7, 20, 20, 20]
    const float* varw0 = (const float*)d_in[4];   // [20, 1, 20]
    const float* varw = (const float*)d_in[5];    // [7, 20, 20, 20]
    float* out = (float*)d_out;                   // [N, 2]

    int N = in_sizes[0] / N_DIM;
    int ntiles = N / (4 * THREADS);               // 64 for N=32768

    cudaFuncSetAttribute(main_kernel, cudaFuncAttributeMaxDynamicSharedMemorySize,
                         SMEM_BYTES);
    main_kernel<<<P_DIM * 7 * ntiles, THREADS, SMEM_BYTES>>>(X, perm, meanw0, meanw,
                                                             varw0, varw, ntiles);

    reduce1_kernel<<<(P_DIM * N + 255) / 256, 256>>>(N);
    reduce2_kernel<<<(N + 255) / 256, 256>>>(out, N);
}